// round 1
// baseline (speedup 1.0000x reference)
#include <cuda_runtime.h>
#include <cstdint>
#include <cstddef>

#define Bb 256
#define Tt 128
#define Dd 1024
#define Hh 1024
#define BTr (Bb*Tt)            // 32768
#define G3  (3*Hh)             // 3072
#define BTH ((size_t)BTr*Hh)   // 33554432

// Scratch (static device globals: allocation-guard-safe)
__device__ float g_gi[(size_t)BTr * G3];       // 402 MB: x @ W_ih^T + b_ih
__device__ float g_hseq_fallback[BTH];         // 128 MB: only used if out buffer lacks Hseq
__device__ int   g_mask_mode;                  // 0=int32, 1=uint8, 2=float32

// ---------------------------------------------------------------------------
// Detect the storage dtype of the boolean is_init array.
// uint8: values 0/1 at every byte -> nonzero bytes at offsets %4!=0, none >1.
// int32: nonzero bytes only at offsets %4==0, values 0/1.
// float32: 1.0f = 00 00 80 3F -> bytes >1 present.
// ---------------------------------------------------------------------------
__global__ void detect_kernel(const unsigned char* __restrict__ p) {
    __shared__ int s_off, s_gt1;
    if (threadIdx.x == 0) { s_off = 0; s_gt1 = 0; }
    __syncthreads();
    int f_off = 0, f_gt1 = 0;
    for (int i = threadIdx.x; i < 4096; i += 256) {
        unsigned char v = p[i];
        if ((i & 3) != 0 && v) f_off = 1;
        if (v > 1) f_gt1 = 1;
    }
    if (f_off) atomicOr(&s_off, 1);
    if (f_gt1) atomicOr(&s_gt1, 1);
    __syncthreads();
    if (threadIdx.x == 0)
        g_mask_mode = s_gt1 ? 2 : (s_off ? 1 : 0);
}

__device__ __forceinline__ float mask_of(const void* p, int b, int t) {
    int idx = b * Tt + t;
    int mode = g_mask_mode;
    bool is_init;
    if (mode == 2)      is_init = ((const float*)p)[idx] != 0.0f;
    else if (mode == 1) is_init = ((const unsigned char*)p)[idx] != 0;
    else                is_init = ((const int*)p)[idx] != 0;
    return is_init ? 0.0f : 1.0f;
}

// ---------------------------------------------------------------------------
// gi = x @ W_ih^T + b_ih
// C[32768][3072], A row-major [32768][1024], W row-major [3072][1024] (K-contig)
// Tile 128x128, BK=8, 256 threads, 8x8 per-thread microtile.
// ---------------------------------------------------------------------------
__global__ void __launch_bounds__(256) gi_gemm(const float* __restrict__ A,
                                               const float* __restrict__ W,
                                               const float* __restrict__ bias) {
    __shared__ float As[8][128];
    __shared__ float Bs[8][128];
    const int m0 = blockIdx.y * 128;
    const int n0 = blockIdx.x * 128;
    const int tid = threadIdx.x;
    const int tx = tid & 15;       // col group (8 cols each)
    const int ty = tid >> 4;       // row group (8 rows each)
    const int lrow = tid >> 1;     // loader row 0..127
    const int lkq = (tid & 1) * 4; // loader k-quad

    const float* Ap = A + (size_t)(m0 + lrow) * Dd + lkq;
    const float* Wp = W + (size_t)(n0 + lrow) * Dd + lkq;

    float acc[8][8];
#pragma unroll
    for (int i = 0; i < 8; i++)
#pragma unroll
        for (int j = 0; j < 8; j++) acc[i][j] = 0.0f;

    for (int k0 = 0; k0 < Dd; k0 += 8) {
        float4 av = *(const float4*)(Ap + k0);
        float4 wv = *(const float4*)(Wp + k0);
        __syncthreads();
        As[lkq + 0][lrow] = av.x; As[lkq + 1][lrow] = av.y;
        As[lkq + 2][lrow] = av.z; As[lkq + 3][lrow] = av.w;
        Bs[lkq + 0][lrow] = wv.x; Bs[lkq + 1][lrow] = wv.y;
        Bs[lkq + 2][lrow] = wv.z; Bs[lkq + 3][lrow] = wv.w;
        __syncthreads();
#pragma unroll
        for (int k = 0; k < 8; k++) {
            float a[8], b[8];
            *(float4*)(a)     = *(const float4*)&As[k][ty * 8];
            *(float4*)(a + 4) = *(const float4*)&As[k][ty * 8 + 4];
            *(float4*)(b)     = *(const float4*)&Bs[k][tx * 8];
            *(float4*)(b + 4) = *(const float4*)&Bs[k][tx * 8 + 4];
#pragma unroll
            for (int i = 0; i < 8; i++)
#pragma unroll
                for (int j = 0; j < 8; j++)
                    acc[i][j] = fmaf(a[i], b[j], acc[i][j]);
        }
    }
#pragma unroll
    for (int i = 0; i < 8; i++) {
        const int row = m0 + ty * 8 + i;
        float* Cp = g_gi + (size_t)row * G3 + n0 + tx * 8;
#pragma unroll
        for (int j = 0; j < 8; j++)
            Cp[j] = acc[i][j] + bias[n0 + tx * 8 + j];
    }
}

// ---------------------------------------------------------------------------
// One recurrence step: gh = (h*mask) @ W_hh^T + b_hh, fused gate math,
// h_new written into Hseq[:, t, :]. Previous h read from Hseq[:, t-1, :]
// (or hx at t==0).
// Block = 32 batch rows x 64 H-cols x 3 gates, K=1024. 128 threads.
// Thread microtile = 8 rows x 2 cols x 3 gates = 48 accumulators.
// Grid: (Hh/64=16, Bb/32=8) = 128 blocks.
// ---------------------------------------------------------------------------
__global__ void __launch_bounds__(128) step_kernel(const float* __restrict__ Whh,
                                                   const float* __restrict__ bhh,
                                                   const float* __restrict__ hx,
                                                   const void*  __restrict__ isin,
                                                   float* __restrict__ Hseq,
                                                   int t) {
    __shared__ float Hs[16][32];    // [k][row]
    __shared__ float Ws[16][192];   // [k][g*64 + col]
    const int b0 = blockIdx.y * 32;
    const int c0 = blockIdx.x * 64;
    const int tid = threadIdx.x;
    const int ct = tid & 31;        // col group (2 cols each)
    const int rt = tid >> 5;        // row group (8 rows each)
    const int lr  = tid >> 2;       // loader row 0..31
    const int lkq = (tid & 3) * 4;  // loader k-quad

    const float* hbase; size_t hstride;
    if (t == 0) { hbase = hx; hstride = Hh; }
    else        { hbase = Hseq + (size_t)(t - 1) * Hh; hstride = (size_t)Tt * Hh; }

    const float mload = mask_of(isin, b0 + lr, t);
    const float* hrow = hbase + (size_t)(b0 + lr) * hstride;

    float acc[3][8][2];
#pragma unroll
    for (int g = 0; g < 3; g++)
#pragma unroll
        for (int i = 0; i < 8; i++) { acc[g][i][0] = 0.0f; acc[g][i][1] = 0.0f; }

    for (int k0 = 0; k0 < Hh; k0 += 16) {
        float4 hv = *(const float4*)(hrow + k0 + lkq);
        float4 wv[6];
#pragma unroll
        for (int i = 0; i < 6; i++) {
            const int wrow = lr + i * 32;          // 0..191
            const int g = wrow >> 6;
            const int c = wrow & 63;
            wv[i] = *(const float4*)(Whh + (size_t)(g * Hh + c0 + c) * Hh + k0 + lkq);
        }
        __syncthreads();
        Hs[lkq + 0][lr] = hv.x * mload; Hs[lkq + 1][lr] = hv.y * mload;
        Hs[lkq + 2][lr] = hv.z * mload; Hs[lkq + 3][lr] = hv.w * mload;
#pragma unroll
        for (int i = 0; i < 6; i++) {
            const int wrow = lr + i * 32;
            Ws[lkq + 0][wrow] = wv[i].x; Ws[lkq + 1][wrow] = wv[i].y;
            Ws[lkq + 2][wrow] = wv[i].z; Ws[lkq + 3][wrow] = wv[i].w;
        }
        __syncthreads();
#pragma unroll
        for (int k = 0; k < 16; k++) {
            float h[8];
            *(float4*)(h)     = *(const float4*)&Hs[k][rt * 8];
            *(float4*)(h + 4) = *(const float4*)&Hs[k][rt * 8 + 4];
            float2 w0 = *(const float2*)&Ws[k][      ct * 2];
            float2 w1 = *(const float2*)&Ws[k][ 64 + ct * 2];
            float2 w2 = *(const float2*)&Ws[k][128 + ct * 2];
#pragma unroll
            for (int i = 0; i < 8; i++) {
                acc[0][i][0] = fmaf(h[i], w0.x, acc[0][i][0]);
                acc[0][i][1] = fmaf(h[i], w0.y, acc[0][i][1]);
                acc[1][i][0] = fmaf(h[i], w1.x, acc[1][i][0]);
                acc[1][i][1] = fmaf(h[i], w1.y, acc[1][i][1]);
                acc[2][i][0] = fmaf(h[i], w2.x, acc[2][i][0]);
                acc[2][i][1] = fmaf(h[i], w2.y, acc[2][i][1]);
            }
        }
    }

    // Epilogue: gates + h update
    const int gc0 = c0 + ct * 2;
    float br[2] = { bhh[gc0],          bhh[gc0 + 1] };
    float bz[2] = { bhh[Hh + gc0],     bhh[Hh + gc0 + 1] };
    float bn[2] = { bhh[2 * Hh + gc0], bhh[2 * Hh + gc0 + 1] };
#pragma unroll
    for (int i = 0; i < 8; i++) {
        const int gb = b0 + rt * 8 + i;
        const float m = mask_of(isin, gb, t);
        const float* hr_ptr = hbase + (size_t)gb * hstride;
        const float* gip = g_gi + ((size_t)gb * Tt + t) * G3;
        float* outp = Hseq + ((size_t)gb * Tt + t) * Hh;
#pragma unroll
        for (int j = 0; j < 2; j++) {
            const int gc = gc0 + j;
            const float hr_v = acc[0][i][j] + br[j];
            const float hz_v = acc[1][i][j] + bz[j];
            const float hn_v = acc[2][i][j] + bn[j];
            const float ir  = gip[gc];
            const float iz  = gip[Hh + gc];
            const float inn = gip[2 * Hh + gc];
            const float r = 1.0f / (1.0f + __expf(-(ir + hr_v)));
            const float z = 1.0f / (1.0f + __expf(-(iz + hz_v)));
            const float n = tanhf(inn + r * hn_v);
            const float h_old = hr_ptr[gc] * m;
            outp[gc] = (1.0f - z) * n + z * h_old;
        }
    }
}

// ---------------------------------------------------------------------------
// Y = LayerNorm(Hseq)*g + b + x*sigmoid(res_gate). One block per (b,t) row.
// ---------------------------------------------------------------------------
__global__ void __launch_bounds__(256) ln_kernel(const float* __restrict__ Hseq,
                                                 const float* __restrict__ x,
                                                 const float* __restrict__ gg,
                                                 const float* __restrict__ bbta,
                                                 const float* __restrict__ resg,
                                                 float* __restrict__ Y) {
    const int row = blockIdx.x;
    const float* hp = Hseq + (size_t)row * Hh;
    const int c = threadIdx.x * 4;
    float4 v = *(const float4*)(hp + c);
    float s  = v.x + v.y + v.z + v.w;
    float ss = v.x * v.x + v.y * v.y + v.z * v.z + v.w * v.w;
#pragma unroll
    for (int o = 16; o > 0; o >>= 1) {
        s  += __shfl_xor_sync(0xffffffff, s,  o);
        ss += __shfl_xor_sync(0xffffffff, ss, o);
    }
    __shared__ float sm[8], sm2[8];
    const int w = threadIdx.x >> 5, l = threadIdx.x & 31;
    if (l == 0) { sm[w] = s; sm2[w] = ss; }
    __syncthreads();
    if (threadIdx.x == 0) {
        float a = 0.0f, b2 = 0.0f;
#pragma unroll
        for (int i = 0; i < 8; i++) { a += sm[i]; b2 += sm2[i]; }
        sm[0] = a; sm2[0] = b2;
    }
    __syncthreads();
    const float mu  = sm[0] * (1.0f / Hh);
    const float var = sm2[0] * (1.0f / Hh) - mu * mu;
    const float inv = rsqrtf(var + 1e-5f);

    const float4 xv = *(const float4*)(x + (size_t)row * Dd + c);
    const float4 gv = *(const float4*)(gg + c);
    const float4 bv = *(const float4*)(bbta + c);
    const float4 rv = *(const float4*)(resg + c);
    float4 y;
    y.x = (v.x - mu) * inv * gv.x + bv.x + xv.x * (1.0f / (1.0f + __expf(-rv.x)));
    y.y = (v.y - mu) * inv * gv.y + bv.y + xv.y * (1.0f / (1.0f + __expf(-rv.y)));
    y.z = (v.z - mu) * inv * gv.z + bv.z + xv.z * (1.0f / (1.0f + __expf(-rv.z)));
    y.w = (v.w - mu) * inv * gv.w + bv.w + xv.w * (1.0f / (1.0f + __expf(-rv.w)));
    *(float4*)(Y + (size_t)row * Hh + c) = y;
}

// ---------------------------------------------------------------------------
extern "C" void kernel_launch(void* const* d_in, const int* in_sizes, int n_in,
                              void* d_out, int out_size) {
    const float* x    = (const float*)d_in[0];
    const float* hx   = (const float*)d_in[1];
    const void*  isin =               d_in[2];
    const float* Wih  = (const float*)d_in[3];
    const float* Whh  = (const float*)d_in[4];
    const float* bih  = (const float*)d_in[5];
    const float* bhh  = (const float*)d_in[6];
    const float* lng  = (const float*)d_in[7];
    const float* lnb  = (const float*)d_in[8];
    const float* rg   = (const float*)d_in[9];

    float* Y = (float*)d_out;
    float* Hseq;
    if ((size_t)out_size >= 2 * BTH) {
        Hseq = Y + BTH;               // output is (Y, Hseq) concatenated
    } else {
        void* p = nullptr;
        cudaGetSymbolAddress(&p, g_hseq_fallback);   // pure host query, capture-safe
        Hseq = (float*)p;
    }

    detect_kernel<<<1, 256>>>((const unsigned char*)isin);
    gi_gemm<<<dim3(G3 / 128, BTr / 128), 256>>>(x, Wih, bih);
    for (int t = 0; t < Tt; t++)
        step_kernel<<<dim3(Hh / 64, Bb / 32), 128>>>(Whh, bhh, hx, isin, Hseq, t);
    ln_kernel<<<BTr, 256>>>(Hseq, x, lng, lnb, rg, Y);
}

// round 3
// speedup vs baseline: 2.7159x; 2.7159x over previous
#include <cuda_runtime.h>
#include <cuda_bf16.h>
#include <cstdint>
#include <cstddef>

#define Bb 256
#define Tt 128
#define Dd 1024
#define Hh 1024
#define BTr (Bb*Tt)            // 32768
#define G3  (3*Hh)             // 3072
#define BTH ((size_t)BTr*Hh)

// ------------------------- device scratch (no mallocs) ----------------------
__device__ float g_gi[(size_t)BTr * G3];                  // 402 MB
__device__ float g_hseq_fallback[BTH];                    // 128 MB
__device__ int   g_mask_mode;
__device__ __align__(16) __nv_bfloat16 g_whi[(size_t)G3 * Hh];     // W_hh hi
__device__ __align__(16) __nv_bfloat16 g_wlo[(size_t)G3 * Hh];     // W_hh lo
__device__ __align__(16) __nv_bfloat16 g_wihhi[(size_t)G3 * Dd];   // W_ih hi
__device__ __align__(16) __nv_bfloat16 g_wihlo[(size_t)G3 * Dd];   // W_ih lo
__device__ __align__(16) __nv_bfloat16 g_xhi[(size_t)BTr * Dd];    // x hi (64 MB)
__device__ __align__(16) __nv_bfloat16 g_xlo[(size_t)BTr * Dd];    // x lo
__device__ __align__(16) __nv_bfloat16 g_hhi[2][(size_t)Bb * Hh];  // h ping-pong hi
__device__ __align__(16) __nv_bfloat16 g_hlo[2][(size_t)Bb * Hh];  // h ping-pong lo

// ------------------------------ PTX helpers (base sm_103 safe) ---------------
__device__ __forceinline__ uint32_t smem_u32(const void* p) {
    uint32_t a;
    asm("{ .reg .u64 t; cvta.to.shared.u64 t, %1; cvt.u32.u64 %0, t; }"
        : "=r"(a) : "l"(p));
    return a;
}
__device__ __forceinline__ void cp16(uint32_t dst, const void* src) {
    asm volatile("cp.async.cg.shared.global [%0], [%1], 16;"
                 :: "r"(dst), "l"(src) : "memory");
}
#define CP_COMMIT() asm volatile("cp.async.commit_group;" ::: "memory")
#define CP_WAIT(n)  asm volatile("cp.async.wait_group %0;" :: "n"(n) : "memory")

__device__ __forceinline__ void ldsm_x4(uint32_t* r, uint32_t addr) {
    asm volatile("ldmatrix.sync.aligned.m8n8.x4.shared.b16 {%0,%1,%2,%3}, [%4];"
                 : "=r"(r[0]), "=r"(r[1]), "=r"(r[2]), "=r"(r[3]) : "r"(addr));
}
__device__ __forceinline__ void ldsm_x2(uint32_t* r, uint32_t addr) {
    asm volatile("ldmatrix.sync.aligned.m8n8.x2.shared.b16 {%0,%1}, [%2];"
                 : "=r"(r[0]), "=r"(r[1]) : "r"(addr));
}
__device__ __forceinline__ void mma16816(float* d, const uint32_t* a, const uint32_t* b) {
    asm volatile("mma.sync.aligned.m16n8k16.row.col.f32.bf16.bf16.f32 "
                 "{%0,%1,%2,%3}, {%4,%5,%6,%7}, {%8,%9}, {%0,%1,%2,%3};"
                 : "+f"(d[0]), "+f"(d[1]), "+f"(d[2]), "+f"(d[3])
                 : "r"(a[0]), "r"(a[1]), "r"(a[2]), "r"(a[3]), "r"(b[0]), "r"(b[1]));
}
__device__ __forceinline__ uint32_t pack2(__nv_bfloat16 a, __nv_bfloat16 b) {
    return ((uint32_t)__bfloat16_as_ushort(b) << 16) | __bfloat16_as_ushort(a);
}

// --------------------------- mask dtype detection ----------------------------
__global__ void detect_kernel(const unsigned char* __restrict__ p) {
    __shared__ int s_off, s_gt1;
    if (threadIdx.x == 0) { s_off = 0; s_gt1 = 0; }
    __syncthreads();
    int f_off = 0, f_gt1 = 0;
    for (int i = threadIdx.x; i < 4096; i += 256) {
        unsigned char v = p[i];
        if ((i & 3) != 0 && v) f_off = 1;
        if (v > 1) f_gt1 = 1;
    }
    if (f_off) atomicOr(&s_off, 1);
    if (f_gt1) atomicOr(&s_gt1, 1);
    __syncthreads();
    if (threadIdx.x == 0) g_mask_mode = s_gt1 ? 2 : (s_off ? 1 : 0);
}
__device__ __forceinline__ float mask_of(const void* p, int b, int t) {
    int idx = b * Tt + t;
    int mode = g_mask_mode;
    bool ii;
    if (mode == 2)      ii = ((const float*)p)[idx] != 0.0f;
    else if (mode == 1) ii = ((const unsigned char*)p)[idx] != 0;
    else                ii = ((const int*)p)[idx] != 0;
    return ii ? 0.0f : 1.0f;
}

// --------------------- prep: fp32 -> bf16 hi/lo splits -----------------------
__global__ void __launch_bounds__(256) split_pair(const float4* __restrict__ src,
                                                  __nv_bfloat16* __restrict__ hi,
                                                  __nv_bfloat16* __restrict__ lo) {
    size_t i = (size_t)blockIdx.x * blockDim.x + threadIdx.x;
    float4 v = src[i];
    __nv_bfloat16 h0 = __float2bfloat16(v.x), h1 = __float2bfloat16(v.y);
    __nv_bfloat16 h2 = __float2bfloat16(v.z), h3 = __float2bfloat16(v.w);
    __nv_bfloat16 l0 = __float2bfloat16(v.x - __bfloat162float(h0));
    __nv_bfloat16 l1 = __float2bfloat16(v.y - __bfloat162float(h1));
    __nv_bfloat16 l2 = __float2bfloat16(v.z - __bfloat162float(h2));
    __nv_bfloat16 l3 = __float2bfloat16(v.w - __bfloat162float(h3));
    ((uint2*)hi)[i] = make_uint2(pack2(h0, h1), pack2(h2, h3));
    ((uint2*)lo)[i] = make_uint2(pack2(l0, l1), pack2(l2, l3));
}

// -------------------- gi = x @ W_ih^T + b_ih  (HMMA bf16x3) ------------------
// Block tile 128x128, 256 thr (8 warps 2x4), warp tile 64x32, KC=32, cp.async x2.
#define GI_AB 10240                     // 128 rows * 80B (pitch 40 elems)
#define GI_BUF (4 * GI_AB)              // Ahi,Alo,Bhi,Blo
#define GI_SMEM (2 * GI_BUF)            // 81920

__global__ void __launch_bounds__(256) gi_gemm(const float* __restrict__ bias) {
    extern __shared__ char sm[];
    const uint32_t sb = smem_u32(sm);
    const int tid = threadIdx.x, lane = tid & 31, wid = tid >> 5;
    const int wm = wid >> 2, wn = wid & 3;
    const int n0 = blockIdx.x * 128, m0 = blockIdx.y * 128;

    float acc[4][4][4];
#pragma unroll
    for (int i = 0; i < 4; i++)
#pragma unroll
        for (int j = 0; j < 4; j++)
#pragma unroll
            for (int k = 0; k < 4; k++) acc[i][j][k] = 0.0f;

#define GI_ISSUE(ch) do {                                                        \
    const int _c = (ch);                                                         \
    const uint32_t base = sb + (_c & 1) * GI_BUF;                                \
    _Pragma("unroll")                                                            \
    for (int it = 0; it < 4; it++) {                                             \
        int i = tid + it * 256, part = i >> 9, j = i & 511, r = j >> 2, q = j & 3; \
        cp16(base + part * GI_AB + r * 80 + q * 16,                              \
             (part ? g_xlo : g_xhi) + (size_t)(m0 + r) * Dd + _c * 32 + q * 8);  \
    }                                                                            \
    _Pragma("unroll")                                                            \
    for (int it = 0; it < 4; it++) {                                             \
        int i = tid + it * 256, part = i >> 9, j = i & 511, r = j >> 2, q = j & 3; \
        cp16(base + (2 + part) * GI_AB + r * 80 + q * 16,                        \
             (part ? g_wihlo : g_wihhi) + (size_t)(n0 + r) * Dd + _c * 32 + q * 8); \
    }                                                                            \
    CP_COMMIT(); } while (0)

    GI_ISSUE(0);
    for (int ch = 0; ch < 32; ch++) {
        if (ch + 1 < 32) { GI_ISSUE(ch + 1); CP_WAIT(1); }
        else             { CP_WAIT(0); }
        __syncthreads();
        const uint32_t base = sb + (ch & 1) * GI_BUF;
        const uint32_t aHi = base, aLo = base + GI_AB;
        const uint32_t bHi = base + 2 * GI_AB, bLo = base + 3 * GI_AB;
#pragma unroll
        for (int ks = 0; ks < 2; ks++) {
            uint32_t ah[4][4], bh[4][2];
#pragma unroll
            for (int ma = 0; ma < 4; ma++)
                ldsm_x4(ah[ma], aHi + ((wm * 64 + ma * 16 + (lane & 15)) * 40
                                       + ks * 16 + (lane >> 4) * 8) * 2);
#pragma unroll
            for (int na = 0; na < 4; na++) {
                int l = lane & 15;
                ldsm_x2(bh[na], bHi + ((wn * 32 + na * 8 + (l & 7)) * 40
                                       + ks * 16 + (l >> 3) * 8) * 2);
            }
#pragma unroll
            for (int ma = 0; ma < 4; ma++)
#pragma unroll
                for (int na = 0; na < 4; na++) mma16816(acc[ma][na], ah[ma], bh[na]);
            {
                uint32_t bl[4][2];
#pragma unroll
                for (int na = 0; na < 4; na++) {
                    int l = lane & 15;
                    ldsm_x2(bl[na], bLo + ((wn * 32 + na * 8 + (l & 7)) * 40
                                           + ks * 16 + (l >> 3) * 8) * 2);
                }
#pragma unroll
                for (int ma = 0; ma < 4; ma++)
#pragma unroll
                    for (int na = 0; na < 4; na++) mma16816(acc[ma][na], ah[ma], bl[na]);
            }
            {
                uint32_t al[4][4];
#pragma unroll
                for (int ma = 0; ma < 4; ma++)
                    ldsm_x4(al[ma], aLo + ((wm * 64 + ma * 16 + (lane & 15)) * 40
                                           + ks * 16 + (lane >> 4) * 8) * 2);
#pragma unroll
                for (int ma = 0; ma < 4; ma++)
#pragma unroll
                    for (int na = 0; na < 4; na++) mma16816(acc[ma][na], al[ma], bh[na]);
            }
        }
        __syncthreads();
    }
    // epilogue: direct global float2 stores with bias
#pragma unroll
    for (int ma = 0; ma < 4; ma++) {
        const int row = m0 + wm * 64 + ma * 16 + (lane >> 2);
#pragma unroll
        for (int na = 0; na < 4; na++) {
            const int col = n0 + wn * 32 + na * 8 + (lane & 3) * 2;
            const float b0 = bias[col], b1 = bias[col + 1];
            float* p = g_gi + (size_t)row * G3 + col;
            *(float2*)p = make_float2(acc[ma][na][0] + b0, acc[ma][na][1] + b1);
            *(float2*)(p + 8 * (size_t)G3) =
                make_float2(acc[ma][na][2] + b0, acc[ma][na][3] + b1);
        }
    }
}

// ---------------------- recurrent step (HMMA bf16x3, fused) ------------------
// Block tile M=64 (batch) x N=96 (32 H-cols x 3 gates). Grid (32, 4) = 128.
// 8 warps (2 M x 4 N), warp tile 32x24. Mask applied in epilogue (per-row scalar).
#define SC_AB 5120                       // 64 rows * 80B
#define SC_BB 7680                       // 96 rows * 80B
#define SC_BUF (2 * SC_AB + 2 * SC_BB)   // 25600
#define SC_MASK (2 * SC_BUF)             // 51200
#define SC_SMEM (SC_MASK + 256)          // 51456

__global__ void __launch_bounds__(256)
scan_step(const float* __restrict__ bhh, const float* __restrict__ hx,
          const void* __restrict__ isin, float* __restrict__ Hseq, int t) {
    extern __shared__ char sm[];
    const uint32_t sb = smem_u32(sm);
    float* maskS = (float*)(sm + SC_MASK);
    const int tid = threadIdx.x, lane = tid & 31, wid = tid >> 5;
    const int wm = wid >> 2, wn = wid & 3;
    const int c0 = blockIdx.x * 32, m0 = blockIdx.y * 64;

    const __nv_bfloat16* hhi = g_hhi[t & 1];
    const __nv_bfloat16* hlo = g_hlo[t & 1];
    __nv_bfloat16* hhi_o = g_hhi[(t & 1) ^ 1];
    __nv_bfloat16* hlo_o = g_hlo[(t & 1) ^ 1];

    if (tid < 64) maskS[tid] = mask_of(isin, m0 + tid, t);

    float acc[2][3][4];
#pragma unroll
    for (int i = 0; i < 2; i++)
#pragma unroll
        for (int j = 0; j < 3; j++)
#pragma unroll
            for (int k = 0; k < 4; k++) acc[i][j][k] = 0.0f;

#define SC_ISSUE(ch) do {                                                        \
    const int _c = (ch);                                                         \
    const uint32_t base = sb + (_c & 1) * SC_BUF;                                \
    { int r = tid >> 2, q = tid & 3;                                             \
      cp16(base + r * 80 + q * 16, hhi + (size_t)(m0 + r) * Hh + _c * 32 + q * 8); \
      cp16(base + SC_AB + r * 80 + q * 16,                                       \
           hlo + (size_t)(m0 + r) * Hh + _c * 32 + q * 8); }                     \
    _Pragma("unroll")                                                            \
    for (int it = 0; it < 3; it++) {                                             \
        int i = tid + it * 256;                                                  \
        int part = (i >= 384), j = i - part * 384, r = j >> 2, q = j & 3;        \
        int g = r >> 5, cc = r & 31;                                             \
        cp16(base + 2 * SC_AB + part * SC_BB + r * 80 + q * 16,                  \
             (part ? g_wlo : g_whi) + (size_t)(g * Hh + c0 + cc) * Hh + _c * 32 + q * 8); \
    }                                                                            \
    CP_COMMIT(); } while (0)

    SC_ISSUE(0);
    for (int ch = 0; ch < 32; ch++) {
        if (ch + 1 < 32) { SC_ISSUE(ch + 1); CP_WAIT(1); }
        else             { CP_WAIT(0); }
        __syncthreads();
        const uint32_t base = sb + (ch & 1) * SC_BUF;
        const uint32_t aHi = base, aLo = base + SC_AB;
        const uint32_t bHi = base + 2 * SC_AB, bLo = bHi + SC_BB;
#pragma unroll
        for (int ks = 0; ks < 2; ks++) {
            uint32_t ah[2][4], bh[3][2];
#pragma unroll
            for (int ma = 0; ma < 2; ma++)
                ldsm_x4(ah[ma], aHi + ((wm * 32 + ma * 16 + (lane & 15)) * 40
                                       + ks * 16 + (lane >> 4) * 8) * 2);
#pragma unroll
            for (int na = 0; na < 3; na++) {
                int l = lane & 15;
                ldsm_x2(bh[na], bHi + ((wn * 24 + na * 8 + (l & 7)) * 40
                                       + ks * 16 + (l >> 3) * 8) * 2);
            }
#pragma unroll
            for (int ma = 0; ma < 2; ma++)
#pragma unroll
                for (int na = 0; na < 3; na++) mma16816(acc[ma][na], ah[ma], bh[na]);
            {
                uint32_t bl[3][2];
#pragma unroll
                for (int na = 0; na < 3; na++) {
                    int l = lane & 15;
                    ldsm_x2(bl[na], bLo + ((wn * 24 + na * 8 + (l & 7)) * 40
                                           + ks * 16 + (l >> 3) * 8) * 2);
                }
#pragma unroll
                for (int ma = 0; ma < 2; ma++)
#pragma unroll
                    for (int na = 0; na < 3; na++) mma16816(acc[ma][na], ah[ma], bl[na]);
            }
            {
                uint32_t al[2][4];
#pragma unroll
                for (int ma = 0; ma < 2; ma++)
                    ldsm_x4(al[ma], aLo + ((wm * 32 + ma * 16 + (lane & 15)) * 40
                                           + ks * 16 + (lane >> 4) * 8) * 2);
#pragma unroll
                for (int ma = 0; ma < 2; ma++)
#pragma unroll
                    for (int na = 0; na < 3; na++) mma16816(acc[ma][na], al[ma], bh[na]);
            }
        }
        __syncthreads();
    }
    // stage gh (64 x 96 fp32, pitch 100) over buffer 0 region
    float* ghS = (float*)sm;
#pragma unroll
    for (int ma = 0; ma < 2; ma++) {
        const int row = wm * 32 + ma * 16 + (lane >> 2);
#pragma unroll
        for (int na = 0; na < 3; na++) {
            const int col = wn * 24 + na * 8 + (lane & 3) * 2;
            *(float2*)(ghS + row * 100 + col) = make_float2(acc[ma][na][0], acc[ma][na][1]);
            *(float2*)(ghS + (row + 8) * 100 + col) = make_float2(acc[ma][na][2], acc[ma][na][3]);
        }
    }
    __syncthreads();
    // fused epilogue: gates + update. 64 rows x 32 cols; thread = (r, 8-col group)
    {
        const int r = tid & 63, cg = tid >> 6;
        const int brow = m0 + r;
        const float m = maskS[r];
        const float* gip = g_gi + ((size_t)brow * Tt + t) * G3 + c0;
        const float* holdp = (t == 0) ? (hx + (size_t)brow * Hh + c0)
                                      : (Hseq + ((size_t)brow * Tt + (t - 1)) * Hh + c0);
        float* outp = Hseq + ((size_t)brow * Tt + t) * Hh + c0;
        __nv_bfloat16* po = hhi_o + (size_t)brow * Hh + c0;
        __nv_bfloat16* qo = hlo_o + (size_t)brow * Hh + c0;
#pragma unroll
        for (int j = 0; j < 8; j++) {
            const int c = cg * 8 + j;
            const int col = c0 + c;
            const float hrv = m * ghS[r * 100 + c]      + bhh[col];
            const float hzv = m * ghS[r * 100 + 32 + c] + bhh[Hh + col];
            const float hnv = m * ghS[r * 100 + 64 + c] + bhh[2 * Hh + col];
            const float ir  = gip[c];
            const float iz  = gip[Hh + c];
            const float inn = gip[2 * Hh + c];
            const float rg = 1.0f / (1.0f + __expf(-(ir + hrv)));
            const float z  = 1.0f / (1.0f + __expf(-(iz + hzv)));
            const float n  = tanhf(inn + rg * hnv);
            const float h  = (1.0f - z) * n + z * (holdp[c] * m);
            outp[c] = h;
            const __nv_bfloat16 hb = __float2bfloat16(h);
            po[c] = hb;
            qo[c] = __float2bfloat16(h - __bfloat162float(hb));
        }
    }
}

// --------------------------- LayerNorm + residual ----------------------------
__global__ void __launch_bounds__(256) ln_kernel(const float* __restrict__ Hseq,
                                                 const float* __restrict__ x,
                                                 const float* __restrict__ gg,
                                                 const float* __restrict__ bbta,
                                                 const float* __restrict__ resg,
                                                 float* __restrict__ Y) {
    const int row = blockIdx.x;
    const float* hp = Hseq + (size_t)row * Hh;
    const int c = threadIdx.x * 4;
    float4 v = *(const float4*)(hp + c);
    float s  = v.x + v.y + v.z + v.w;
    float ss = v.x * v.x + v.y * v.y + v.z * v.z + v.w * v.w;
#pragma unroll
    for (int o = 16; o > 0; o >>= 1) {
        s  += __shfl_xor_sync(0xffffffff, s,  o);
        ss += __shfl_xor_sync(0xffffffff, ss, o);
    }
    __shared__ float smw[8], sm2[8];
    const int w = threadIdx.x >> 5, l = threadIdx.x & 31;
    if (l == 0) { smw[w] = s; sm2[w] = ss; }
    __syncthreads();
    if (threadIdx.x == 0) {
        float a = 0.0f, b2 = 0.0f;
#pragma unroll
        for (int i = 0; i < 8; i++) { a += smw[i]; b2 += sm2[i]; }
        smw[0] = a; sm2[0] = b2;
    }
    __syncthreads();
    const float mu  = smw[0] * (1.0f / Hh);
    const float var = sm2[0] * (1.0f / Hh) - mu * mu;
    const float inv = rsqrtf(var + 1e-5f);
    const float4 xv = *(const float4*)(x + (size_t)row * Dd + c);
    const float4 gv = *(const float4*)(gg + c);
    const float4 bv = *(const float4*)(bbta + c);
    const float4 rv = *(const float4*)(resg + c);
    float4 y;
    y.x = (v.x - mu) * inv * gv.x + bv.x + xv.x * (1.0f / (1.0f + __expf(-rv.x)));
    y.y = (v.y - mu) * inv * gv.y + bv.y + xv.y * (1.0f / (1.0f + __expf(-rv.y)));
    y.z = (v.z - mu) * inv * gv.z + bv.z + xv.z * (1.0f / (1.0f + __expf(-rv.z)));
    y.w = (v.w - mu) * inv * gv.w + bv.w + xv.w * (1.0f / (1.0f + __expf(-rv.w)));
    *(float4*)(Y + (size_t)row * Hh + c) = y;
}

// ---------------------------------------------------------------------------
extern "C" void kernel_launch(void* const* d_in, const int* in_sizes, int n_in,
                              void* d_out, int out_size) {
    const float* x    = (const float*)d_in[0];
    const float* hx   = (const float*)d_in[1];
    const void*  isin =               d_in[2];
    const float* Wih  = (const float*)d_in[3];
    const float* Whh  = (const float*)d_in[4];
    const float* bih  = (const float*)d_in[5];
    const float* bhh  = (const float*)d_in[6];
    const float* lng  = (const float*)d_in[7];
    const float* lnb  = (const float*)d_in[8];
    const float* rg   = (const float*)d_in[9];

    float* Y = (float*)d_out;
    float* Hseq;
    if ((size_t)out_size >= 2 * BTH) {
        Hseq = Y + BTH;
    } else {
        void* p = nullptr;
        cudaGetSymbolAddress(&p, g_hseq_fallback);
        Hseq = (float*)p;
    }

    void *p_whi, *p_wlo, *p_wihhi, *p_wihlo, *p_xhi, *p_xlo, *p_hhi, *p_hlo;
    cudaGetSymbolAddress(&p_whi, g_whi);
    cudaGetSymbolAddress(&p_wlo, g_wlo);
    cudaGetSymbolAddress(&p_wihhi, g_wihhi);
    cudaGetSymbolAddress(&p_wihlo, g_wihlo);
    cudaGetSymbolAddress(&p_xhi, g_xhi);
    cudaGetSymbolAddress(&p_xlo, g_xlo);
    cudaGetSymbolAddress(&p_hhi, g_hhi);
    cudaGetSymbolAddress(&p_hlo, g_hlo);

    cudaFuncSetAttribute(gi_gemm, cudaFuncAttributeMaxDynamicSharedMemorySize, GI_SMEM);
    cudaFuncSetAttribute(scan_step, cudaFuncAttributeMaxDynamicSharedMemorySize, SC_SMEM);

    detect_kernel<<<1, 256>>>((const unsigned char*)isin);
    split_pair<<<((size_t)G3 * Hh / 4) / 256, 256>>>((const float4*)Whh,
        (__nv_bfloat16*)p_whi, (__nv_bfloat16*)p_wlo);
    split_pair<<<((size_t)G3 * Dd / 4) / 256, 256>>>((const float4*)Wih,
        (__nv_bfloat16*)p_wihhi, (__nv_bfloat16*)p_wihlo);
    split_pair<<<((size_t)BTr * Dd / 4) / 256, 256>>>((const float4*)x,
        (__nv_bfloat16*)p_xhi, (__nv_bfloat16*)p_xlo);
    split_pair<<<((size_t)Bb * Hh / 4) / 256, 256>>>((const float4*)hx,
        (__nv_bfloat16*)p_hhi, (__nv_bfloat16*)p_hlo);

    gi_gemm<<<dim3(G3 / 128, BTr / 128), 256, GI_SMEM>>>(bih);
    for (int t = 0; t < Tt; t++)
        scan_step<<<dim3(Hh / 32, Bb / 64), 256, SC_SMEM>>>(bhh, hx, isin, Hseq, t);
    ln_kernel<<<BTr, 256>>>(Hseq, x, lng, lnb, rg, Y);
}

// round 5
// speedup vs baseline: 2.7845x; 1.0253x over previous
#include <cuda_runtime.h>
#include <cuda_bf16.h>
#include <cstdint>
#include <cstddef>

#define Bb 256
#define Tt 128
#define Dd 1024
#define Hh 1024
#define BTr (Bb*Tt)            // 32768
#define G3  (3*Hh)             // 3072
#define BTH ((size_t)BTr*Hh)

// ------------------------- device scratch (no mallocs) ----------------------
__device__ float g_gi[(size_t)BTr * G3];                  // 402 MB
__device__ float g_hseq_fallback[BTH];                    // 128 MB
__device__ int   g_mask_mode;
__device__ unsigned int g_ctr[4];                         // scan group barriers
__device__ __align__(16) __nv_bfloat16 g_whi[(size_t)G3 * Hh];     // W_hh hi
__device__ __align__(16) __nv_bfloat16 g_wlo[(size_t)G3 * Hh];     // W_hh lo
__device__ __align__(16) __nv_bfloat16 g_wihhi[(size_t)G3 * Dd];   // W_ih hi
__device__ __align__(16) __nv_bfloat16 g_wihlo[(size_t)G3 * Dd];   // W_ih lo
__device__ __align__(16) __nv_bfloat16 g_xhi[(size_t)BTr * Dd];    // x hi
__device__ __align__(16) __nv_bfloat16 g_xlo[(size_t)BTr * Dd];    // x lo
__device__ __align__(16) __nv_bfloat16 g_hhi[2][(size_t)Bb * Hh];  // h ping-pong hi
__device__ __align__(16) __nv_bfloat16 g_hlo[2][(size_t)Bb * Hh];  // h ping-pong lo

// ------------------------------ PTX helpers (base sm_103 safe) ---------------
__device__ __forceinline__ uint32_t smem_u32(const void* p) {
    uint32_t a;
    asm("{ .reg .u64 t; cvta.to.shared.u64 t, %1; cvt.u32.u64 %0, t; }"
        : "=r"(a) : "l"(p));
    return a;
}
__device__ __forceinline__ void cp16(uint32_t dst, const void* src) {
    asm volatile("cp.async.cg.shared.global [%0], [%1], 16;"
                 :: "r"(dst), "l"(src) : "memory");
}
#define CP_COMMIT() asm volatile("cp.async.commit_group;" ::: "memory")
#define CP_WAIT(n)  asm volatile("cp.async.wait_group %0;" :: "n"(n) : "memory")

__device__ __forceinline__ void ldsm_x4(uint32_t* r, uint32_t addr) {
    asm volatile("ldmatrix.sync.aligned.m8n8.x4.shared.b16 {%0,%1,%2,%3}, [%4];"
                 : "=r"(r[0]), "=r"(r[1]), "=r"(r[2]), "=r"(r[3]) : "r"(addr));
}
__device__ __forceinline__ void ldsm_x2(uint32_t* r, uint32_t addr) {
    asm volatile("ldmatrix.sync.aligned.m8n8.x2.shared.b16 {%0,%1}, [%2];"
                 : "=r"(r[0]), "=r"(r[1]) : "r"(addr));
}
__device__ __forceinline__ void mma16816(float* d, const uint32_t* a, const uint32_t* b) {
    asm volatile("mma.sync.aligned.m16n8k16.row.col.f32.bf16.bf16.f32 "
                 "{%0,%1,%2,%3}, {%4,%5,%6,%7}, {%8,%9}, {%0,%1,%2,%3};"
                 : "+f"(d[0]), "+f"(d[1]), "+f"(d[2]), "+f"(d[3])
                 : "r"(a[0]), "r"(a[1]), "r"(a[2]), "r"(a[3]), "r"(b[0]), "r"(b[1]));
}
__device__ __forceinline__ uint32_t pack2(__nv_bfloat16 a, __nv_bfloat16 b) {
    return ((uint32_t)__bfloat16_as_ushort(b) << 16) | __bfloat16_as_ushort(a);
}
__device__ __forceinline__ unsigned int ld_acq(const unsigned int* p) {
    unsigned int v;
    asm volatile("ld.acquire.gpu.global.u32 %0, [%1];" : "=r"(v) : "l"(p) : "memory");
    return v;
}
__device__ __forceinline__ void red_release(unsigned int* p, unsigned int v) {
    asm volatile("red.release.gpu.global.add.u32 [%0], %1;" :: "l"(p), "r"(v) : "memory");
}

// --------------------------- mask dtype detection ----------------------------
__global__ void detect_kernel(const unsigned char* __restrict__ p) {
    __shared__ int s_off, s_gt1;
    if (threadIdx.x == 0) { s_off = 0; s_gt1 = 0; }
    __syncthreads();
    int f_off = 0, f_gt1 = 0;
    for (int i = threadIdx.x; i < 4096; i += 256) {
        unsigned char v = p[i];
        if ((i & 3) != 0 && v) f_off = 1;
        if (v > 1) f_gt1 = 1;
    }
    if (f_off) atomicOr(&s_off, 1);
    if (f_gt1) atomicOr(&s_gt1, 1);
    __syncthreads();
    if (threadIdx.x == 0) g_mask_mode = s_gt1 ? 2 : (s_off ? 1 : 0);
}
__global__ void reset_ctr_kernel() {
    if (threadIdx.x < 4) g_ctr[threadIdx.x] = 0u;
}
__device__ __forceinline__ float mask_of(const void* p, int b, int t) {
    int idx = b * Tt + t;
    int mode = g_mask_mode;
    bool ii;
    if (mode == 2)      ii = ((const float*)p)[idx] != 0.0f;
    else if (mode == 1) ii = ((const unsigned char*)p)[idx] != 0;
    else                ii = ((const int*)p)[idx] != 0;
    return ii ? 0.0f : 1.0f;
}

// --------------------- prep: fp32 -> bf16 hi/lo splits -----------------------
__global__ void __launch_bounds__(256) split_pair(const float4* __restrict__ src,
                                                  __nv_bfloat16* __restrict__ hi,
                                                  __nv_bfloat16* __restrict__ lo) {
    size_t i = (size_t)blockIdx.x * blockDim.x + threadIdx.x;
    float4 v = src[i];
    __nv_bfloat16 h0 = __float2bfloat16(v.x), h1 = __float2bfloat16(v.y);
    __nv_bfloat16 h2 = __float2bfloat16(v.z), h3 = __float2bfloat16(v.w);
    __nv_bfloat16 l0 = __float2bfloat16(v.x - __bfloat162float(h0));
    __nv_bfloat16 l1 = __float2bfloat16(v.y - __bfloat162float(h1));
    __nv_bfloat16 l2 = __float2bfloat16(v.z - __bfloat162float(h2));
    __nv_bfloat16 l3 = __float2bfloat16(v.w - __bfloat162float(h3));
    ((uint2*)hi)[i] = make_uint2(pack2(h0, h1), pack2(h2, h3));
    ((uint2*)lo)[i] = make_uint2(pack2(l0, l1), pack2(l2, l3));
}

// -------------------- gi = x @ W_ih^T + b_ih  (HMMA bf16x3) ------------------
#define GI_AB 10240
#define GI_BUF (4 * GI_AB)
#define GI_SMEM (2 * GI_BUF)

__global__ void __launch_bounds__(256) gi_gemm(const float* __restrict__ bias) {
    extern __shared__ char sm[];
    const uint32_t sb = smem_u32(sm);
    const int tid = threadIdx.x, lane = tid & 31, wid = tid >> 5;
    const int wm = wid >> 2, wn = wid & 3;
    const int n0 = blockIdx.x * 128, m0 = blockIdx.y * 128;

    float acc[4][4][4];
#pragma unroll
    for (int i = 0; i < 4; i++)
#pragma unroll
        for (int j = 0; j < 4; j++)
#pragma unroll
            for (int k = 0; k < 4; k++) acc[i][j][k] = 0.0f;

#define GI_ISSUE(ch) do {                                                        \
    const int _c = (ch);                                                         \
    const uint32_t base = sb + (_c & 1) * GI_BUF;                                \
    _Pragma("unroll")                                                            \
    for (int it = 0; it < 4; it++) {                                             \
        int i = tid + it * 256, part = i >> 9, j = i & 511, r = j >> 2, q = j & 3; \
        cp16(base + part * GI_AB + r * 80 + q * 16,                              \
             (part ? g_xlo : g_xhi) + (size_t)(m0 + r) * Dd + _c * 32 + q * 8);  \
    }                                                                            \
    _Pragma("unroll")                                                            \
    for (int it = 0; it < 4; it++) {                                             \
        int i = tid + it * 256, part = i >> 9, j = i & 511, r = j >> 2, q = j & 3; \
        cp16(base + (2 + part) * GI_AB + r * 80 + q * 16,                        \
             (part ? g_wihlo : g_wihhi) + (size_t)(n0 + r) * Dd + _c * 32 + q * 8); \
    }                                                                            \
    CP_COMMIT(); } while (0)

    GI_ISSUE(0);
    for (int ch = 0; ch < 32; ch++) {
        if (ch + 1 < 32) { GI_ISSUE(ch + 1); CP_WAIT(1); }
        else             { CP_WAIT(0); }
        __syncthreads();
        const uint32_t base = sb + (ch & 1) * GI_BUF;
        const uint32_t aHi = base, aLo = base + GI_AB;
        const uint32_t bHi = base + 2 * GI_AB, bLo = base + 3 * GI_AB;
#pragma unroll
        for (int ks = 0; ks < 2; ks++) {
            uint32_t ah[4][4], bh[4][2];
#pragma unroll
            for (int ma = 0; ma < 4; ma++)
                ldsm_x4(ah[ma], aHi + ((wm * 64 + ma * 16 + (lane & 15)) * 40
                                       + ks * 16 + (lane >> 4) * 8) * 2);
#pragma unroll
            for (int na = 0; na < 4; na++) {
                int l = lane & 15;
                ldsm_x2(bh[na], bHi + ((wn * 32 + na * 8 + (l & 7)) * 40
                                       + ks * 16 + (l >> 3) * 8) * 2);
            }
#pragma unroll
            for (int ma = 0; ma < 4; ma++)
#pragma unroll
                for (int na = 0; na < 4; na++) mma16816(acc[ma][na], ah[ma], bh[na]);
            {
                uint32_t bl[4][2];
#pragma unroll
                for (int na = 0; na < 4; na++) {
                    int l = lane & 15;
                    ldsm_x2(bl[na], bLo + ((wn * 32 + na * 8 + (l & 7)) * 40
                                           + ks * 16 + (l >> 3) * 8) * 2);
                }
#pragma unroll
                for (int ma = 0; ma < 4; ma++)
#pragma unroll
                    for (int na = 0; na < 4; na++) mma16816(acc[ma][na], ah[ma], bl[na]);
            }
            {
                uint32_t al[4][4];
#pragma unroll
                for (int ma = 0; ma < 4; ma++)
                    ldsm_x4(al[ma], aLo + ((wm * 64 + ma * 16 + (lane & 15)) * 40
                                           + ks * 16 + (lane >> 4) * 8) * 2);
#pragma unroll
                for (int ma = 0; ma < 4; ma++)
#pragma unroll
                    for (int na = 0; na < 4; na++) mma16816(acc[ma][na], al[ma], bh[na]);
            }
        }
        __syncthreads();
    }
#pragma unroll
    for (int ma = 0; ma < 4; ma++) {
        const int row = m0 + wm * 64 + ma * 16 + (lane >> 2);
#pragma unroll
        for (int na = 0; na < 4; na++) {
            const int col = n0 + wn * 32 + na * 8 + (lane & 3) * 2;
            const float b0 = bias[col], b1 = bias[col + 1];
            float* p = g_gi + (size_t)row * G3 + col;
            *(float2*)p = make_float2(acc[ma][na][0] + b0, acc[ma][na][1] + b1);
            *(float2*)(p + 8 * (size_t)G3) =
                make_float2(acc[ma][na][2] + b0, acc[ma][na][3] + b1);
        }
    }
}

// ---------------- persistent recurrent scan (all 128 steps) ------------------
// Grid (32, 4) = 128 resident blocks. Block tile M=64 x N=96 (32 cols x 3 gates).
// Distance-1 double-buffer pipeline: at chunk ch, issue chunk ch+1 into the
// OPPOSITE buffer, CP_WAIT(1) drains the group that loaded chunk ch.
// W chunk 0 for the next step is prefetched at ch==31 (buf0 W region; last
// read at ch==30). Pre-step issues only A(0).
#define SC_AB 5120                       // 64 rows * 80B
#define SC_BB 7680                       // 96 rows * 80B
#define SC_BUF (2 * SC_AB + 2 * SC_BB)   // 25600: [Ahi|Alo|Whi|Wlo]
#define PS_GH (2 * SC_BUF)               // gh staging: 64 x 100 fp32 = 25600
#define PS_MASK (PS_GH + 25600)          // 76800
#define PS_SMEM (PS_MASK + 256)          // 77056

__global__ void __launch_bounds__(256)
scan_all(const float* __restrict__ bhh, const float* __restrict__ hx,
         const void* __restrict__ isin, float* __restrict__ Hseq) {
    extern __shared__ char sm[];
    const uint32_t sb = smem_u32(sm);
    float* ghS = (float*)(sm + PS_GH);
    float* maskS = (float*)(sm + PS_MASK);
    const int tid = threadIdx.x, lane = tid & 31, wid = tid >> 5;
    const int wm = wid >> 2, wn = wid & 3;
    const int c0 = blockIdx.x * 32, m0 = blockIdx.y * 64;
    unsigned int* ctr = &g_ctr[blockIdx.y];

#define PS_ISSUE_A(cc, hhi, hlo) do {                                            \
    const uint32_t base = sb + ((cc) & 1) * SC_BUF;                              \
    int r = tid >> 2, q = tid & 3;                                               \
    cp16(base + r * 80 + q * 16, (hhi) + (size_t)(m0 + r) * Hh + (cc) * 32 + q * 8); \
    cp16(base + SC_AB + r * 80 + q * 16,                                         \
         (hlo) + (size_t)(m0 + r) * Hh + (cc) * 32 + q * 8); } while (0)

#define PS_ISSUE_W(cc) do {                                                      \
    const uint32_t base = sb + ((cc) & 1) * SC_BUF;                              \
    _Pragma("unroll")                                                            \
    for (int it = 0; it < 3; it++) {                                             \
        int i = tid + it * 256;                                                  \
        int part = (i >= 384), j = i - part * 384, r = j >> 2, q = j & 3;        \
        int g = r >> 5, cc2 = r & 31;                                            \
        cp16(base + 2 * SC_AB + part * SC_BB + r * 80 + q * 16,                  \
             (part ? g_wlo : g_whi) + (size_t)(g * Hh + c0 + cc2) * Hh + (cc) * 32 + q * 8); \
    } } while (0)

    // prefetch W chunk 0 for step 0 (group: G_pref)
    PS_ISSUE_W(0);
    CP_COMMIT();

    for (int t = 0; t < Tt; t++) {
        const __nv_bfloat16* hhi = g_hhi[t & 1];
        const __nv_bfloat16* hlo = g_hlo[t & 1];
        __nv_bfloat16* hhi_o = g_hhi[(t & 1) ^ 1];
        __nv_bfloat16* hlo_o = g_hlo[(t & 1) ^ 1];

        // wait for h[t-1] from all 32 blocks of this batch group (tid0 spins)
        if (t > 0) {
            if (tid == 0) {
                const unsigned int target = 32u * (unsigned int)t;
                while (ld_acq(ctr) < target) __nanosleep(64);
            }
            __syncthreads();
        }
        if (tid < 64) maskS[tid] = mask_of(isin, m0 + tid, t);

        // pre-step: A chunk 0 (W chunk 0 already in flight / resident)
        PS_ISSUE_A(0, hhi, hlo);
        CP_COMMIT();

        float acc[2][3][4];
#pragma unroll
        for (int i = 0; i < 2; i++)
#pragma unroll
            for (int j = 0; j < 3; j++)
#pragma unroll
                for (int k = 0; k < 4; k++) acc[i][j][k] = 0.0f;

        for (int ch = 0; ch < 32; ch++) {
            if (ch < 31) {
                // issue chunk ch+1 -> buffer (ch+1)&1 (opposite of read buffer)
                PS_ISSUE_A(ch + 1, hhi, hlo);
                PS_ISSUE_W(ch + 1);
                CP_COMMIT();
                CP_WAIT(1);     // drains everything up to the group of chunk ch
            } else if (t + 1 < Tt) {
                // ch==31: prefetch next step's W chunk 0 into buf0 (last read ch==30)
                PS_ISSUE_W(0);
                CP_COMMIT();
                CP_WAIT(1);     // drains chunk-31 group, leaves prefetch pending
            } else {
                CP_WAIT(0);
            }
            __syncthreads();
            const uint32_t base = sb + (ch & 1) * SC_BUF;
            const uint32_t aHi = base, aLo = base + SC_AB;
            const uint32_t bHi = base + 2 * SC_AB, bLo = bHi + SC_BB;
#pragma unroll
            for (int ks = 0; ks < 2; ks++) {
                uint32_t ah[2][4], bh[3][2];
#pragma unroll
                for (int ma = 0; ma < 2; ma++)
                    ldsm_x4(ah[ma], aHi + ((wm * 32 + ma * 16 + (lane & 15)) * 40
                                           + ks * 16 + (lane >> 4) * 8) * 2);
#pragma unroll
                for (int na = 0; na < 3; na++) {
                    int l = lane & 15;
                    ldsm_x2(bh[na], bHi + ((wn * 24 + na * 8 + (l & 7)) * 40
                                           + ks * 16 + (l >> 3) * 8) * 2);
                }
#pragma unroll
                for (int ma = 0; ma < 2; ma++)
#pragma unroll
                    for (int na = 0; na < 3; na++) mma16816(acc[ma][na], ah[ma], bh[na]);
                {
                    uint32_t bl[3][2];
#pragma unroll
                    for (int na = 0; na < 3; na++) {
                        int l = lane & 15;
                        ldsm_x2(bl[na], bLo + ((wn * 24 + na * 8 + (l & 7)) * 40
                                               + ks * 16 + (l >> 3) * 8) * 2);
                    }
#pragma unroll
                    for (int ma = 0; ma < 2; ma++)
#pragma unroll
                        for (int na = 0; na < 3; na++) mma16816(acc[ma][na], ah[ma], bl[na]);
                }
                {
                    uint32_t al[2][4];
#pragma unroll
                    for (int ma = 0; ma < 2; ma++)
                        ldsm_x4(al[ma], aLo + ((wm * 32 + ma * 16 + (lane & 15)) * 40
                                               + ks * 16 + (lane >> 4) * 8) * 2);
#pragma unroll
                    for (int ma = 0; ma < 2; ma++)
#pragma unroll
                        for (int na = 0; na < 3; na++) mma16816(acc[ma][na], al[ma], bh[na]);
                }
            }
            __syncthreads();
        }

        // stage gh (64 x 96 fp32, pitch 100) in dedicated region
#pragma unroll
        for (int ma = 0; ma < 2; ma++) {
            const int row = wm * 32 + ma * 16 + (lane >> 2);
#pragma unroll
            for (int na = 0; na < 3; na++) {
                const int col = wn * 24 + na * 8 + (lane & 3) * 2;
                *(float2*)(ghS + row * 100 + col) =
                    make_float2(acc[ma][na][0], acc[ma][na][1]);
                *(float2*)(ghS + (row + 8) * 100 + col) =
                    make_float2(acc[ma][na][2], acc[ma][na][3]);
            }
        }
        __syncthreads();

        // fused epilogue: gates + update. thread = (row r, 8-col group cg)
        {
            const int r = tid & 63, cg = tid >> 6;
            const int brow = m0 + r;
            const float m = maskS[r];
            const float* gip = g_gi + ((size_t)brow * Tt + t) * G3 + c0;
            const float* holdp = (t == 0) ? (hx + (size_t)brow * Hh + c0)
                                          : (Hseq + ((size_t)brow * Tt + (t - 1)) * Hh + c0);
            float* outp = Hseq + ((size_t)brow * Tt + t) * Hh + c0;
            __nv_bfloat16* po = hhi_o + (size_t)brow * Hh + c0;
            __nv_bfloat16* qo = hlo_o + (size_t)brow * Hh + c0;
#pragma unroll
            for (int j = 0; j < 8; j++) {
                const int c = cg * 8 + j;
                const int col = c0 + c;
                const float hrv = m * ghS[r * 100 + c]      + bhh[col];
                const float hzv = m * ghS[r * 100 + 32 + c] + bhh[Hh + col];
                const float hnv = m * ghS[r * 100 + 64 + c] + bhh[2 * Hh + col];
                const float ir  = gip[c];
                const float iz  = gip[Hh + c];
                const float inn = gip[2 * Hh + c];
                const float rg = 1.0f / (1.0f + __expf(-(ir + hrv)));
                const float z  = 1.0f / (1.0f + __expf(-(iz + hzv)));
                const float n  = tanhf(inn + rg * hnv);
                const float h  = (1.0f - z) * n + z * (holdp[c] * m);
                outp[c] = h;
                const __nv_bfloat16 hb = __float2bfloat16(h);
                po[c] = hb;
                qo[c] = __float2bfloat16(h - __bfloat162float(hb));
            }
        }
        // release: publish h_new to the group, then arrive (release semantics)
        __threadfence();
        __syncthreads();
        if (tid == 0 && t + 1 < Tt) red_release(ctr, 1u);
    }
}

// --------------------------- LayerNorm + residual ----------------------------
__global__ void __launch_bounds__(256) ln_kernel(const float* __restrict__ Hseq,
                                                 const float* __restrict__ x,
                                                 const float* __restrict__ gg,
                                                 const float* __restrict__ bbta,
                                                 const float* __restrict__ resg,
                                                 float* __restrict__ Y) {
    const int row = blockIdx.x;
    const float* hp = Hseq + (size_t)row * Hh;
    const int c = threadIdx.x * 4;
    float4 v = *(const float4*)(hp + c);
    float s  = v.x + v.y + v.z + v.w;
    float ss = v.x * v.x + v.y * v.y + v.z * v.z + v.w * v.w;
#pragma unroll
    for (int o = 16; o > 0; o >>= 1) {
        s  += __shfl_xor_sync(0xffffffff, s,  o);
        ss += __shfl_xor_sync(0xffffffff, ss, o);
    }
    __shared__ float smw[8], sm2[8];
    const int w = threadIdx.x >> 5, l = threadIdx.x & 31;
    if (l == 0) { smw[w] = s; sm2[w] = ss; }
    __syncthreads();
    if (threadIdx.x == 0) {
        float a = 0.0f, b2 = 0.0f;
#pragma unroll
        for (int i = 0; i < 8; i++) { a += smw[i]; b2 += sm2[i]; }
        smw[0] = a; sm2[0] = b2;
    }
    __syncthreads();
    const float mu  = smw[0] * (1.0f / Hh);
    const float var = sm2[0] * (1.0f / Hh) - mu * mu;
    const float inv = rsqrtf(var + 1e-5f);
    const float4 xv = *(const float4*)(x + (size_t)row * Dd + c);
    const float4 gv = *(const float4*)(gg + c);
    const float4 bv = *(const float4*)(bbta + c);
    const float4 rv = *(const float4*)(resg + c);
    float4 y;
    y.x = (v.x - mu) * inv * gv.x + bv.x + xv.x * (1.0f / (1.0f + __expf(-rv.x)));
    y.y = (v.y - mu) * inv * gv.y + bv.y + xv.y * (1.0f / (1.0f + __expf(-rv.y)));
    y.z = (v.z - mu) * inv * gv.z + bv.z + xv.z * (1.0f / (1.0f + __expf(-rv.z)));
    y.w = (v.w - mu) * inv * gv.w + bv.w + xv.w * (1.0f / (1.0f + __expf(-rv.w)));
    *(float4*)(Y + (size_t)row * Hh + c) = y;
}

// ---------------------------------------------------------------------------
extern "C" void kernel_launch(void* const* d_in, const int* in_sizes, int n_in,
                              void* d_out, int out_size) {
    const float* x    = (const float*)d_in[0];
    const float* hx   = (const float*)d_in[1];
    const void*  isin =               d_in[2];
    const float* Wih  = (const float*)d_in[3];
    const float* Whh  = (const float*)d_in[4];
    const float* bih  = (const float*)d_in[5];
    const float* bhh  = (const float*)d_in[6];
    const float* lng  = (const float*)d_in[7];
    const float* lnb  = (const float*)d_in[8];
    const float* rg   = (const float*)d_in[9];

    float* Y = (float*)d_out;
    float* Hseq;
    if ((size_t)out_size >= 2 * BTH) {
        Hseq = Y + BTH;
    } else {
        void* p = nullptr;
        cudaGetSymbolAddress(&p, g_hseq_fallback);
        Hseq = (float*)p;
    }

    void *p_whi, *p_wlo, *p_wihhi, *p_wihlo, *p_xhi, *p_xlo, *p_hhi, *p_hlo;
    cudaGetSymbolAddress(&p_whi, g_whi);
    cudaGetSymbolAddress(&p_wlo, g_wlo);
    cudaGetSymbolAddress(&p_wihhi, g_wihhi);
    cudaGetSymbolAddress(&p_wihlo, g_wihlo);
    cudaGetSymbolAddress(&p_xhi, g_xhi);
    cudaGetSymbolAddress(&p_xlo, g_xlo);
    cudaGetSymbolAddress(&p_hhi, g_hhi);
    cudaGetSymbolAddress(&p_hlo, g_hlo);

    cudaFuncSetAttribute(gi_gemm, cudaFuncAttributeMaxDynamicSharedMemorySize, GI_SMEM);
    cudaFuncSetAttribute(scan_all, cudaFuncAttributeMaxDynamicSharedMemorySize, PS_SMEM);

    detect_kernel<<<1, 256>>>((const unsigned char*)isin);
    reset_ctr_kernel<<<1, 32>>>();
    split_pair<<<((size_t)G3 * Hh / 4) / 256, 256>>>((const float4*)Whh,
        (__nv_bfloat16*)p_whi, (__nv_bfloat16*)p_wlo);
    split_pair<<<((size_t)G3 * Dd / 4) / 256, 256>>>((const float4*)Wih,
        (__nv_bfloat16*)p_wihhi, (__nv_bfloat16*)p_wihlo);
    split_pair<<<((size_t)BTr * Dd / 4) / 256, 256>>>((const float4*)x,
        (__nv_bfloat16*)p_xhi, (__nv_bfloat16*)p_xlo);
    split_pair<<<((size_t)Bb * Hh / 4) / 256, 256>>>((const float4*)hx,
        (__nv_bfloat16*)p_hhi, (__nv_bfloat16*)p_hlo);

    gi_gemm<<<dim3(G3 / 128, BTr / 128), 256, GI_SMEM>>>(bih);
    scan_all<<<dim3(Hh / 32, Bb / 64), 256, PS_SMEM>>>(bhh, hx, isin, Hseq);
    ln_kernel<<<BTr, 256>>>(Hseq, x, lng, lnb, rg, Y);
}

// round 6
// speedup vs baseline: 3.4770x; 1.2487x over previous
#include <cuda_runtime.h>
#include <cuda_bf16.h>
#include <cstdint>
#include <cstddef>

#define Bb 256
#define Tt 128
#define Dd 1024
#define Hh 1024
#define BTr (Bb*Tt)            // 32768
#define G3  (3*Hh)             // 3072
#define BTH ((size_t)BTr*Hh)

// ------------------------- device scratch (no mallocs) ----------------------
__device__ float g_gi[(size_t)BTr * G3];                  // 402 MB
__device__ float g_hseq_fallback[BTH];                    // 128 MB
__device__ int   g_mask_mode;
__device__ unsigned int g_ctr[4];                         // scan group barriers
__device__ __align__(16) __nv_bfloat16 g_whi[(size_t)G3 * Hh];     // W_hh hi
__device__ __align__(16) __nv_bfloat16 g_wlo[(size_t)G3 * Hh];     // W_hh lo
__device__ __align__(16) __nv_bfloat16 g_wihhi[(size_t)G3 * Dd];   // W_ih hi
__device__ __align__(16) __nv_bfloat16 g_wihlo[(size_t)G3 * Dd];   // W_ih lo
__device__ __align__(16) __nv_bfloat16 g_xhi[(size_t)BTr * Dd];    // x hi
__device__ __align__(16) __nv_bfloat16 g_xlo[(size_t)BTr * Dd];    // x lo
__device__ __align__(16) __nv_bfloat16 g_hhi[2][(size_t)Bb * Hh];  // h ping-pong hi
__device__ __align__(16) __nv_bfloat16 g_hlo[2][(size_t)Bb * Hh];  // h ping-pong lo

// ------------------------------ PTX helpers (base sm_103 safe) ---------------
__device__ __forceinline__ uint32_t smem_u32(const void* p) {
    uint32_t a;
    asm("{ .reg .u64 t; cvta.to.shared.u64 t, %1; cvt.u32.u64 %0, t; }"
        : "=r"(a) : "l"(p));
    return a;
}
__device__ __forceinline__ void cp16(uint32_t dst, const void* src) {
    asm volatile("cp.async.cg.shared.global [%0], [%1], 16;"
                 :: "r"(dst), "l"(src) : "memory");
}
#define CP_COMMIT() asm volatile("cp.async.commit_group;" ::: "memory")
#define CP_WAIT(n)  asm volatile("cp.async.wait_group %0;" :: "n"(n) : "memory")

__device__ __forceinline__ void ldsm_x4(uint32_t* r, uint32_t addr) {
    asm volatile("ldmatrix.sync.aligned.m8n8.x4.shared.b16 {%0,%1,%2,%3}, [%4];"
                 : "=r"(r[0]), "=r"(r[1]), "=r"(r[2]), "=r"(r[3]) : "r"(addr));
}
__device__ __forceinline__ void ldsm_x2(uint32_t* r, uint32_t addr) {
    asm volatile("ldmatrix.sync.aligned.m8n8.x2.shared.b16 {%0,%1}, [%2];"
                 : "=r"(r[0]), "=r"(r[1]) : "r"(addr));
}
__device__ __forceinline__ void mma16816(float* d, const uint32_t* a, const uint32_t* b) {
    asm volatile("mma.sync.aligned.m16n8k16.row.col.f32.bf16.bf16.f32 "
                 "{%0,%1,%2,%3}, {%4,%5,%6,%7}, {%8,%9}, {%0,%1,%2,%3};"
                 : "+f"(d[0]), "+f"(d[1]), "+f"(d[2]), "+f"(d[3])
                 : "r"(a[0]), "r"(a[1]), "r"(a[2]), "r"(a[3]), "r"(b[0]), "r"(b[1]));
}
__device__ __forceinline__ uint32_t pack2(__nv_bfloat16 a, __nv_bfloat16 b) {
    return ((uint32_t)__bfloat16_as_ushort(b) << 16) | __bfloat16_as_ushort(a);
}
__device__ __forceinline__ unsigned int ld_acq(const unsigned int* p) {
    unsigned int v;
    asm volatile("ld.acquire.gpu.global.u32 %0, [%1];" : "=r"(v) : "l"(p) : "memory");
    return v;
}
__device__ __forceinline__ void red_release(unsigned int* p, unsigned int v) {
    asm volatile("red.release.gpu.global.add.u32 [%0], %1;" :: "l"(p), "r"(v) : "memory");
}

// --------------------------- mask dtype detection ----------------------------
__global__ void detect_kernel(const unsigned char* __restrict__ p) {
    __shared__ int s_off, s_gt1;
    if (threadIdx.x == 0) { s_off = 0; s_gt1 = 0; }
    __syncthreads();
    int f_off = 0, f_gt1 = 0;
    for (int i = threadIdx.x; i < 4096; i += 256) {
        unsigned char v = p[i];
        if ((i & 3) != 0 && v) f_off = 1;
        if (v > 1) f_gt1 = 1;
    }
    if (f_off) atomicOr(&s_off, 1);
    if (f_gt1) atomicOr(&s_gt1, 1);
    __syncthreads();
    if (threadIdx.x == 0) g_mask_mode = s_gt1 ? 2 : (s_off ? 1 : 0);
}
__global__ void reset_ctr_kernel() {
    if (threadIdx.x < 4) g_ctr[threadIdx.x] = 0u;
}
__device__ __forceinline__ float mask_of(const void* p, int b, int t) {
    int idx = b * Tt + t;
    int mode = g_mask_mode;
    bool ii;
    if (mode == 2)      ii = ((const float*)p)[idx] != 0.0f;
    else if (mode == 1) ii = ((const unsigned char*)p)[idx] != 0;
    else                ii = ((const int*)p)[idx] != 0;
    return ii ? 0.0f : 1.0f;
}

// --------------------- prep: fp32 -> bf16 hi/lo splits (fused) ---------------
__device__ __forceinline__ void split_one(const float4* src, __nv_bfloat16* hi,
                                          __nv_bfloat16* lo, size_t i) {
    float4 v = src[i];
    __nv_bfloat16 h0 = __float2bfloat16(v.x), h1 = __float2bfloat16(v.y);
    __nv_bfloat16 h2 = __float2bfloat16(v.z), h3 = __float2bfloat16(v.w);
    __nv_bfloat16 l0 = __float2bfloat16(v.x - __bfloat162float(h0));
    __nv_bfloat16 l1 = __float2bfloat16(v.y - __bfloat162float(h1));
    __nv_bfloat16 l2 = __float2bfloat16(v.z - __bfloat162float(h2));
    __nv_bfloat16 l3 = __float2bfloat16(v.w - __bfloat162float(h3));
    ((uint2*)hi)[i] = make_uint2(pack2(h0, h1), pack2(h2, h3));
    ((uint2*)lo)[i] = make_uint2(pack2(l0, l1), pack2(l2, l3));
}
// prepA: W_hh (blocks [0,3072)) + W_ih (blocks [3072,6144))
__global__ void __launch_bounds__(256) prepA(const float* __restrict__ Whh,
                                             const float* __restrict__ Wih) {
    int b = blockIdx.x;
    if (b < 3072) {
        size_t i = (size_t)b * 256 + threadIdx.x;
        split_one((const float4*)Whh, g_whi, g_wlo, i);
    } else {
        size_t i = (size_t)(b - 3072) * 256 + threadIdx.x;
        split_one((const float4*)Wih, g_wihhi, g_wihlo, i);
    }
}
// prepB: x (blocks [0,32768)) + hx (blocks [32768,33024))
__global__ void __launch_bounds__(256) prepB(const float* __restrict__ x,
                                             const float* __restrict__ hx) {
    int b = blockIdx.x;
    if (b < 32768) {
        size_t i = (size_t)b * 256 + threadIdx.x;
        split_one((const float4*)x, g_xhi, g_xlo, i);
    } else {
        size_t i = (size_t)(b - 32768) * 256 + threadIdx.x;
        split_one((const float4*)hx, g_hhi[0], g_hlo[0], i);
    }
}

// -------------------- gi = x @ W_ih^T + b_ih  (HMMA bf16x3) ------------------
#define GI_AB 10240
#define GI_BUF (4 * GI_AB)
#define GI_SMEM (2 * GI_BUF)

__global__ void __launch_bounds__(256) gi_gemm(const float* __restrict__ bias) {
    extern __shared__ char sm[];
    const uint32_t sb = smem_u32(sm);
    const int tid = threadIdx.x, lane = tid & 31, wid = tid >> 5;
    const int wm = wid >> 2, wn = wid & 3;
    const int n0 = blockIdx.x * 128, m0 = blockIdx.y * 128;

    float acc[4][4][4];
#pragma unroll
    for (int i = 0; i < 4; i++)
#pragma unroll
        for (int j = 0; j < 4; j++)
#pragma unroll
            for (int k = 0; k < 4; k++) acc[i][j][k] = 0.0f;

#define GI_ISSUE(ch) do {                                                        \
    const int _c = (ch);                                                         \
    const uint32_t base = sb + (_c & 1) * GI_BUF;                                \
    _Pragma("unroll")                                                            \
    for (int it = 0; it < 4; it++) {                                             \
        int i = tid + it * 256, part = i >> 9, j = i & 511, r = j >> 2, q = j & 3; \
        cp16(base + part * GI_AB + r * 80 + q * 16,                              \
             (part ? g_xlo : g_xhi) + (size_t)(m0 + r) * Dd + _c * 32 + q * 8);  \
    }                                                                            \
    _Pragma("unroll")                                                            \
    for (int it = 0; it < 4; it++) {                                             \
        int i = tid + it * 256, part = i >> 9, j = i & 511, r = j >> 2, q = j & 3; \
        cp16(base + (2 + part) * GI_AB + r * 80 + q * 16,                        \
             (part ? g_wihlo : g_wihhi) + (size_t)(n0 + r) * Dd + _c * 32 + q * 8); \
    }                                                                            \
    CP_COMMIT(); } while (0)

    GI_ISSUE(0);
    for (int ch = 0; ch < 32; ch++) {
        if (ch + 1 < 32) { GI_ISSUE(ch + 1); CP_WAIT(1); }
        else             { CP_WAIT(0); }
        __syncthreads();
        const uint32_t base = sb + (ch & 1) * GI_BUF;
        const uint32_t aHi = base, aLo = base + GI_AB;
        const uint32_t bHi = base + 2 * GI_AB, bLo = base + 3 * GI_AB;
#pragma unroll
        for (int ks = 0; ks < 2; ks++) {
            uint32_t ah[4][4], bh[4][2];
#pragma unroll
            for (int ma = 0; ma < 4; ma++)
                ldsm_x4(ah[ma], aHi + ((wm * 64 + ma * 16 + (lane & 15)) * 40
                                       + ks * 16 + (lane >> 4) * 8) * 2);
#pragma unroll
            for (int na = 0; na < 4; na++) {
                int l = lane & 15;
                ldsm_x2(bh[na], bHi + ((wn * 32 + na * 8 + (l & 7)) * 40
                                       + ks * 16 + (l >> 3) * 8) * 2);
            }
#pragma unroll
            for (int ma = 0; ma < 4; ma++)
#pragma unroll
                for (int na = 0; na < 4; na++) mma16816(acc[ma][na], ah[ma], bh[na]);
            {
                uint32_t bl[4][2];
#pragma unroll
                for (int na = 0; na < 4; na++) {
                    int l = lane & 15;
                    ldsm_x2(bl[na], bLo + ((wn * 32 + na * 8 + (l & 7)) * 40
                                           + ks * 16 + (l >> 3) * 8) * 2);
                }
#pragma unroll
                for (int ma = 0; ma < 4; ma++)
#pragma unroll
                    for (int na = 0; na < 4; na++) mma16816(acc[ma][na], ah[ma], bl[na]);
            }
            {
                uint32_t al[4][4];
#pragma unroll
                for (int ma = 0; ma < 4; ma++)
                    ldsm_x4(al[ma], aLo + ((wm * 64 + ma * 16 + (lane & 15)) * 40
                                           + ks * 16 + (lane >> 4) * 8) * 2);
#pragma unroll
                for (int ma = 0; ma < 4; ma++)
#pragma unroll
                    for (int na = 0; na < 4; na++) mma16816(acc[ma][na], al[ma], bh[na]);
            }
        }
        __syncthreads();
    }
#pragma unroll
    for (int ma = 0; ma < 4; ma++) {
        const int row = m0 + wm * 64 + ma * 16 + (lane >> 2);
#pragma unroll
        for (int na = 0; na < 4; na++) {
            const int col = n0 + wn * 32 + na * 8 + (lane & 3) * 2;
            const float b0 = bias[col], b1 = bias[col + 1];
            float* p = g_gi + (size_t)row * G3 + col;
            *(float2*)p = make_float2(acc[ma][na][0] + b0, acc[ma][na][1] + b1);
            *(float2*)(p + 8 * (size_t)G3) =
                make_float2(acc[ma][na][2] + b0, acc[ma][na][3] + b1);
        }
    }
}

// ---------------- persistent recurrent scan (all 128 steps) ------------------
// Grid (32, 4) = 128 resident blocks. Block tile M=64 x N=96.
// B smem rows remapped rr = (cc>>3)*24 + g*8 + (cc&7) so na == gate and each
// thread's 3 na-accumulators are r/z/n of the SAME column -> register epilogue.
// KC=64 (16 chunks, 4 k-steps each), distance-1 double buffer.
// gi tile prefetched per step (h-independent); h_old lives in registers.
#define KC 64
#define NCH 16
#define PITCH 144                          // bytes per smem row (72 bf16)
#define SC_AP 9216                         // 64 * 144 per A part
#define SC_WP 13824                        // 96 * 144 per W part
#define SC_BUF (2 * SC_AP + 2 * SC_WP)     // 46080: [Ahi|Alo|Whi|Wlo]
#define PS_GI  (2 * SC_BUF)                // 92160: gi tile 64 x 96 fp32 (pitch 96)
#define PS_MASK (PS_GI + 24576)            // 116736
#define PS_SMEM (PS_MASK + 256)            // 116992

__global__ void __launch_bounds__(256)
scan_all(const float* __restrict__ bhh, const float* __restrict__ hx,
         const void* __restrict__ isin, float* __restrict__ Hseq) {
    extern __shared__ char sm[];
    const uint32_t sb = smem_u32(sm);
    float* giS = (float*)(sm + PS_GI);
    float* maskS = (float*)(sm + PS_MASK);
    const int tid = threadIdx.x, lane = tid & 31, wid = tid >> 5;
    const int wm = wid >> 2, wn = wid & 3;
    const int c0 = blockIdx.x * 32, m0 = blockIdx.y * 64;
    unsigned int* ctr = &g_ctr[blockIdx.y];

#define PS_ISSUE_A(cc, hhi, hlo) do {                                            \
    const uint32_t base = sb + ((cc) & 1) * SC_BUF;                              \
    _Pragma("unroll")                                                            \
    for (int it = 0; it < 4; it++) {                                             \
        int i = tid + it * 256, part = i >> 9, j = i & 511, r = j >> 3, q = j & 7; \
        cp16(base + part * SC_AP + r * PITCH + q * 16,                           \
             (part ? (hlo) : (hhi)) + (size_t)(m0 + r) * Hh + (cc) * KC + q * 8); \
    } } while (0)

#define PS_ISSUE_W(cc) do {                                                      \
    const uint32_t base = sb + ((cc) & 1) * SC_BUF + 2 * SC_AP;                  \
    _Pragma("unroll")                                                            \
    for (int it = 0; it < 6; it++) {                                             \
        int i = tid + it * 256;                                                  \
        int part = (i >= 768), j = i - part * 768, rs = j >> 3, q = j & 7;       \
        int g = rs >> 5, ccl = rs & 31;                                          \
        int rr = (ccl >> 3) * 24 + g * 8 + (ccl & 7);                            \
        cp16(base + part * SC_WP + rr * PITCH + q * 16,                          \
             (part ? g_wlo : g_whi) + (size_t)(g * Hh + c0 + ccl) * Hh + (cc) * KC + q * 8); \
    } } while (0)

#define PS_ISSUE_GI(tt) do {                                                     \
    _Pragma("unroll")                                                            \
    for (int it = 0; it < 6; it++) {                                             \
        int i = tid + it * 256, r = i / 24, j = i % 24, seg = j >> 3, q = j & 7; \
        cp16(sb + PS_GI + r * 384 + seg * 128 + q * 16,                          \
             g_gi + ((size_t)(m0 + r) * Tt + (tt)) * G3 + seg * 1024 + c0 + q * 4); \
    } } while (0)

    // per-thread invariants for the register epilogue
    const int ccl0 = wn * 8 + (lane & 3) * 2;          // local col of acc[..][..][0]
    float br_[2], bz_[2], bn_[2];
#pragma unroll
    for (int j = 0; j < 2; j++) {
        br_[j] = bhh[c0 + ccl0 + j];
        bz_[j] = bhh[Hh + c0 + ccl0 + j];
        bn_[j] = bhh[2 * Hh + c0 + ccl0 + j];
    }
    // h_old registers: rows wm*32+ma*16+(lane>>2)+rh*8, cols c0+ccl0+j
    float hreg[2][2][2];
#pragma unroll
    for (int ma = 0; ma < 2; ma++)
#pragma unroll
        for (int rh = 0; rh < 2; rh++) {
            const int brow = m0 + wm * 32 + ma * 16 + (lane >> 2) + rh * 8;
            hreg[ma][rh][0] = hx[(size_t)brow * Hh + c0 + ccl0];
            hreg[ma][rh][1] = hx[(size_t)brow * Hh + c0 + ccl0 + 1];
        }

    // prefetch W chunk 0 for step 0
    PS_ISSUE_W(0);
    CP_COMMIT();

    for (int t = 0; t < Tt; t++) {
        const __nv_bfloat16* hhi = g_hhi[t & 1];
        const __nv_bfloat16* hlo = g_hlo[t & 1];
        __nv_bfloat16* hhi_o = g_hhi[(t & 1) ^ 1];
        __nv_bfloat16* hlo_o = g_hlo[(t & 1) ^ 1];

        if (t > 0) {
            if (tid == 0) {
                const unsigned int target = 32u * (unsigned int)t;
                while (ld_acq(ctr) < target) __nanosleep(64);
            }
            __syncthreads();
        }
        if (tid < 64) maskS[tid] = mask_of(isin, m0 + tid, t);

        // pre-step group: A chunk 0 + gi tile (W0 already in flight/resident)
        PS_ISSUE_A(0, hhi, hlo);
        PS_ISSUE_GI(t);
        CP_COMMIT();

        float acc[2][3][4];
#pragma unroll
        for (int i = 0; i < 2; i++)
#pragma unroll
            for (int j = 0; j < 3; j++)
#pragma unroll
                for (int k = 0; k < 4; k++) acc[i][j][k] = 0.0f;

        for (int ch = 0; ch < NCH; ch++) {
            if (ch < NCH - 1) {
                PS_ISSUE_A(ch + 1, hhi, hlo);
                PS_ISSUE_W(ch + 1);
                CP_COMMIT();
                CP_WAIT(1);
            } else if (t + 1 < Tt) {
                PS_ISSUE_W(0);      // next step's W chunk 0 (buf0 W last read ch==14)
                CP_COMMIT();
                CP_WAIT(1);
            } else {
                CP_WAIT(0);
            }
            __syncthreads();
            const uint32_t base = sb + (ch & 1) * SC_BUF;
            const uint32_t aHi = base, aLo = base + SC_AP;
            const uint32_t bHi = base + 2 * SC_AP, bLo = bHi + SC_WP;
#pragma unroll
            for (int ks = 0; ks < 4; ks++) {
                uint32_t ah[2][4], bh[3][2];
#pragma unroll
                for (int ma = 0; ma < 2; ma++)
                    ldsm_x4(ah[ma], aHi + (wm * 32 + ma * 16 + (lane & 15)) * PITCH
                                        + ks * 32 + (lane >> 4) * 16);
#pragma unroll
                for (int na = 0; na < 3; na++) {
                    int l = lane & 15;
                    ldsm_x2(bh[na], bHi + (wn * 24 + na * 8 + (l & 7)) * PITCH
                                        + ks * 32 + (l >> 3) * 16);
                }
#pragma unroll
                for (int ma = 0; ma < 2; ma++)
#pragma unroll
                    for (int na = 0; na < 3; na++) mma16816(acc[ma][na], ah[ma], bh[na]);
                {
                    uint32_t bl[3][2];
#pragma unroll
                    for (int na = 0; na < 3; na++) {
                        int l = lane & 15;
                        ldsm_x2(bl[na], bLo + (wn * 24 + na * 8 + (l & 7)) * PITCH
                                            + ks * 32 + (l >> 3) * 16);
                    }
#pragma unroll
                    for (int ma = 0; ma < 2; ma++)
#pragma unroll
                        for (int na = 0; na < 3; na++) mma16816(acc[ma][na], ah[ma], bl[na]);
                }
                {
                    uint32_t al[2][4];
#pragma unroll
                    for (int ma = 0; ma < 2; ma++)
                        ldsm_x4(al[ma], aLo + (wm * 32 + ma * 16 + (lane & 15)) * PITCH
                                            + ks * 32 + (lane >> 4) * 16);
#pragma unroll
                    for (int ma = 0; ma < 2; ma++)
#pragma unroll
                        for (int na = 0; na < 3; na++) mma16816(acc[ma][na], al[ma], bh[na]);
                }
            }
            __syncthreads();
        }

        // --------- register epilogue: na==gate, cols ccl0..ccl0+1 ---------
#pragma unroll
        for (int ma = 0; ma < 2; ma++)
#pragma unroll
            for (int rh = 0; rh < 2; rh++) {
                const int lr = wm * 32 + ma * 16 + (lane >> 2) + rh * 8;
                const int brow = m0 + lr;
                const float m = maskS[lr];
                float* outp = Hseq + ((size_t)brow * Tt + t) * Hh + c0;
                __nv_bfloat16* po = hhi_o + (size_t)brow * Hh + c0;
                __nv_bfloat16* qo = hlo_o + (size_t)brow * Hh + c0;
#pragma unroll
                for (int j = 0; j < 2; j++) {
                    const int k = rh * 2 + j;
                    const int ccl = ccl0 + j;
                    const float hrv = m * acc[ma][0][k] + br_[j];
                    const float hzv = m * acc[ma][1][k] + bz_[j];
                    const float hnv = m * acc[ma][2][k] + bn_[j];
                    const float ir  = giS[lr * 96 + ccl];
                    const float iz  = giS[lr * 96 + 32 + ccl];
                    const float inn = giS[lr * 96 + 64 + ccl];
                    const float rg = 1.0f / (1.0f + __expf(-(ir + hrv)));
                    const float z  = 1.0f / (1.0f + __expf(-(iz + hzv)));
                    const float n  = tanhf(inn + rg * hnv);
                    const float h  = (1.0f - z) * n + z * (hreg[ma][rh][j] * m);
                    hreg[ma][rh][j] = h;
                    outp[ccl] = h;
                    const __nv_bfloat16 hb = __float2bfloat16(h);
                    po[ccl] = hb;
                    qo[ccl] = __float2bfloat16(h - __bfloat162float(hb));
                }
            }
        __threadfence();
        __syncthreads();
        if (tid == 0 && t + 1 < Tt) red_release(ctr, 1u);
    }
}

// --------------------------- LayerNorm + residual ----------------------------
__global__ void __launch_bounds__(256) ln_kernel(const float* __restrict__ Hseq,
                                                 const float* __restrict__ x,
                                                 const float* __restrict__ gg,
                                                 const float* __restrict__ bbta,
                                                 const float* __restrict__ resg,
                                                 float* __restrict__ Y) {
    const int row = blockIdx.x;
    const float* hp = Hseq + (size_t)row * Hh;
    const int c = threadIdx.x * 4;
    float4 v = *(const float4*)(hp + c);
    float s  = v.x + v.y + v.z + v.w;
    float ss = v.x * v.x + v.y * v.y + v.z * v.z + v.w * v.w;
#pragma unroll
    for (int o = 16; o > 0; o >>= 1) {
        s  += __shfl_xor_sync(0xffffffff, s,  o);
        ss += __shfl_xor_sync(0xffffffff, ss, o);
    }
    __shared__ float smw[8], sm2[8];
    const int w = threadIdx.x >> 5, l = threadIdx.x & 31;
    if (l == 0) { smw[w] = s; sm2[w] = ss; }
    __syncthreads();
    if (threadIdx.x == 0) {
        float a = 0.0f, b2 = 0.0f;
#pragma unroll
        for (int i = 0; i < 8; i++) { a += smw[i]; b2 += sm2[i]; }
        smw[0] = a; sm2[0] = b2;
    }
    __syncthreads();
    const float mu  = smw[0] * (1.0f / Hh);
    const float var = sm2[0] * (1.0f / Hh) - mu * mu;
    const float inv = rsqrtf(var + 1e-5f);
    const float4 xv = *(const float4*)(x + (size_t)row * Dd + c);
    const float4 gv = *(const float4*)(gg + c);
    const float4 bv = *(const float4*)(bbta + c);
    const float4 rv = *(const float4*)(resg + c);
    float4 y;
    y.x = (v.x - mu) * inv * gv.x + bv.x + xv.x * (1.0f / (1.0f + __expf(-rv.x)));
    y.y = (v.y - mu) * inv * gv.y + bv.y + xv.y * (1.0f / (1.0f + __expf(-rv.y)));
    y.z = (v.z - mu) * inv * gv.z + bv.z + xv.z * (1.0f / (1.0f + __expf(-rv.z)));
    y.w = (v.w - mu) * inv * gv.w + bv.w + xv.w * (1.0f / (1.0f + __expf(-rv.w)));
    *(float4*)(Y + (size_t)row * Hh + c) = y;
}

// ---------------------------------------------------------------------------
extern "C" void kernel_launch(void* const* d_in, const int* in_sizes, int n_in,
                              void* d_out, int out_size) {
    const float* x    = (const float*)d_in[0];
    const float* hx   = (const float*)d_in[1];
    const void*  isin =               d_in[2];
    const float* Wih  = (const float*)d_in[3];
    const float* Whh  = (const float*)d_in[4];
    const float* bih  = (const float*)d_in[5];
    const float* bhh  = (const float*)d_in[6];
    const float* lng  = (const float*)d_in[7];
    const float* lnb  = (const float*)d_in[8];
    const float* rg   = (const float*)d_in[9];

    float* Y = (float*)d_out;
    float* Hseq;
    if ((size_t)out_size >= 2 * BTH) {
        Hseq = Y + BTH;
    } else {
        void* p = nullptr;
        cudaGetSymbolAddress(&p, g_hseq_fallback);
        Hseq = (float*)p;
    }

    cudaFuncSetAttribute(gi_gemm, cudaFuncAttributeMaxDynamicSharedMemorySize, GI_SMEM);
    cudaFuncSetAttribute(scan_all, cudaFuncAttributeMaxDynamicSharedMemorySize, PS_SMEM);

    // launch order fixed so ncu (-s 5 -c 1) captures scan_all (index 5)
    detect_kernel<<<1, 256>>>((const unsigned char*)isin);             // 0
    prepA<<<6144, 256>>>(Whh, Wih);                                    // 1
    prepB<<<33024, 256>>>(x, hx);                                      // 2
    gi_gemm<<<dim3(G3 / 128, BTr / 128), 256, GI_SMEM>>>(bih);         // 3
    reset_ctr_kernel<<<1, 32>>>();                                     // 4
    scan_all<<<dim3(Hh / 32, Bb / 64), 256, PS_SMEM>>>(bhh, hx, isin, Hseq); // 5
    ln_kernel<<<BTr, 256>>>(Hseq, x, lng, lnb, rg, Y);                 // 6
}